// round 2
// baseline (speedup 1.0000x reference)
#include <cuda_runtime.h>
#include <math.h>

// Problem constants
static constexpr int B   = 2;
static constexpr int S   = 2048;
static constexpr int H   = 2048;
static constexpr int HQ  = 16;
static constexpr int HKV = 4;
static constexpr int D   = 128;
static constexpr int M   = B * S;          // 4096 token rows
static constexpr int NQ  = HQ * D;         // 2048
static constexpr int NKV = HKV * D;        // 512

// ---------------------------------------------------------------------------
// Scratch (allowed: __device__ globals, no runtime allocation)
// ---------------------------------------------------------------------------
__device__ float g_h [M * H];        // rmsnorm(x)
__device__ float g_q [M * NQ];       // q = h @ Wq^T + bq   [tok, HqD]
__device__ float g_k [M * NKV];
__device__ float g_v [M * NKV];
__device__ float g_qt[M * NQ];       // [B, Hq, S, D] roped
__device__ float g_kt[M * NKV];      // [B, Hkv, S, D] roped
__device__ float g_vt[M * NKV];      // [B, Hkv, S, D]
__device__ float g_ao[M * NQ];       // attention out [B, S, HqD]

// ---------------------------------------------------------------------------
// RMSNorm: one block per token row
// ---------------------------------------------------------------------------
__global__ __launch_bounds__(256) void rmsnorm_kernel(const float* __restrict__ x,
                                                      const float* __restrict__ w)
{
    int row = blockIdx.x;
    const float* xr = x + (size_t)row * H;
    float s = 0.f;
    for (int i = threadIdx.x; i < H; i += 256) { float v = xr[i]; s += v * v; }
    __shared__ float red[8];
    #pragma unroll
    for (int o = 16; o > 0; o >>= 1) s += __shfl_down_sync(0xffffffffu, s, o);
    if ((threadIdx.x & 31) == 0) red[threadIdx.x >> 5] = s;
    __syncthreads();
    if (threadIdx.x < 8) {
        float t = red[threadIdx.x];
        #pragma unroll
        for (int o = 4; o > 0; o >>= 1) t += __shfl_down_sync(0xffu, t, o);
        if (threadIdx.x == 0) red[0] = t;
    }
    __syncthreads();
    float inv = rsqrtf(red[0] / (float)H + 1e-6f);
    float* hr = g_h + (size_t)row * H;
    for (int i = threadIdx.x; i < H; i += 256) hr[i] = xr[i] * inv * w[i];
}

// ---------------------------------------------------------------------------
// NT GEMM: C[m,n] = sum_k A[m,k] * Bm[n,k] (+ bias[n])
// A: [Mdim,Kdim] row-major, Bm: [Ndim,Kdim] row-major. All dims % 128/16 == 0.
// BM=BN=128, BK=16, 256 threads, 8x8 microtile.
// ---------------------------------------------------------------------------
__global__ __launch_bounds__(256) void gemm_nt_kernel(
    const float* __restrict__ A, const float* __restrict__ Bm,
    const float* __restrict__ bias, float* __restrict__ C,
    int Mdim, int Ndim, int Kdim)
{
    __shared__ float As[16][128];
    __shared__ float Bs[16][128];

    int tid = threadIdx.x;
    int bm = blockIdx.y * 128;
    int bn = blockIdx.x * 128;
    int tr = (tid >> 4) * 8;          // 0..120
    int tc = (tid & 15) * 8;          // 0..120
    int lr = tid >> 2;                // 0..63
    int lc = (tid & 3) << 2;          // 0,4,8,12

    const float* Ap = A  + (size_t)(bm + lr) * Kdim + lc;
    const float* Bp = Bm + (size_t)(bn + lr) * Kdim + lc;

    float acc[8][8] = {};

    for (int k0 = 0; k0 < Kdim; k0 += 16) {
        float4 a0 = *(const float4*)(Ap + k0);
        float4 a1 = *(const float4*)(Ap + (size_t)64 * Kdim + k0);
        float4 b0 = *(const float4*)(Bp + k0);
        float4 b1 = *(const float4*)(Bp + (size_t)64 * Kdim + k0);

        As[lc + 0][lr]      = a0.x; As[lc + 1][lr]      = a0.y;
        As[lc + 2][lr]      = a0.z; As[lc + 3][lr]      = a0.w;
        As[lc + 0][lr + 64] = a1.x; As[lc + 1][lr + 64] = a1.y;
        As[lc + 2][lr + 64] = a1.z; As[lc + 3][lr + 64] = a1.w;
        Bs[lc + 0][lr]      = b0.x; Bs[lc + 1][lr]      = b0.y;
        Bs[lc + 2][lr]      = b0.z; Bs[lc + 3][lr]      = b0.w;
        Bs[lc + 0][lr + 64] = b1.x; Bs[lc + 1][lr + 64] = b1.y;
        Bs[lc + 2][lr + 64] = b1.z; Bs[lc + 3][lr + 64] = b1.w;
        __syncthreads();

        #pragma unroll
        for (int k = 0; k < 16; k++) {
            float4 va0 = *(const float4*)&As[k][tr];
            float4 va1 = *(const float4*)&As[k][tr + 4];
            float4 vb0 = *(const float4*)&Bs[k][tc];
            float4 vb1 = *(const float4*)&Bs[k][tc + 4];
            float ar[8] = {va0.x, va0.y, va0.z, va0.w, va1.x, va1.y, va1.z, va1.w};
            float br[8] = {vb0.x, vb0.y, vb0.z, vb0.w, vb1.x, vb1.y, vb1.z, vb1.w};
            #pragma unroll
            for (int i = 0; i < 8; i++)
                #pragma unroll
                for (int j = 0; j < 8; j++)
                    acc[i][j] = fmaf(ar[i], br[j], acc[i][j]);
        }
        __syncthreads();
    }

    float bv[8];
    #pragma unroll
    for (int j = 0; j < 8; j++) bv[j] = bias ? bias[bn + tc + j] : 0.f;

    #pragma unroll
    for (int i = 0; i < 8; i++) {
        float* cp = C + (size_t)(bm + tr + i) * Ndim + bn + tc;
        float4 w0 = make_float4(acc[i][0] + bv[0], acc[i][1] + bv[1],
                                acc[i][2] + bv[2], acc[i][3] + bv[3]);
        float4 w1 = make_float4(acc[i][4] + bv[4], acc[i][5] + bv[5],
                                acc[i][6] + bv[6], acc[i][7] + bv[7]);
        *(float4*)cp = w0;
        *(float4*)(cp + 4) = w1;
    }
}

// ---------------------------------------------------------------------------
// RoPE (rotate-half) + transpose [B,S,Hh,D] -> [B,Hh,S,D]
// one thread per (b, s, h, i<64): handles pair (i, i+64)
// ---------------------------------------------------------------------------
__global__ __launch_bounds__(256) void rope_transpose_kernel(
    const float* __restrict__ in, float* __restrict__ out, int Hh, int do_rope)
{
    int id = blockIdx.x * 256 + threadIdx.x;
    int i  = id & 63;
    int h  = (id >> 6) % Hh;
    int rest = id / (64 * Hh);
    int s  = rest % S;
    int b  = rest / S;

    const float* ip = in + ((size_t)(b * S + s) * Hh + h) * D;
    float t1 = ip[i];
    float t2 = ip[i + 64];
    float* op = out + ((size_t)(b * Hh + h) * S + s) * D;

    if (do_rope) {
        // inv_freq = 10000^{-i/64}
        float inv = exp2f(-(float)i * (13.287712379549449f / 64.0f));
        float ang = (float)s * inv;
        float sn, cs;
        sincosf(ang, &sn, &cs);
        op[i]      = t1 * cs - t2 * sn;
        op[i + 64] = t2 * cs + t1 * sn;
    } else {
        op[i]      = t1;
        op[i + 64] = t2;
    }
}

// ---------------------------------------------------------------------------
// Causal flash attention (fp32). One block = 64 query rows of one (b, hq).
// Smem strides chosen for conflict behavior:
//   Q stride 132 (f4 ld/st, broadcast reads), K stride 129 (scalar STS,
//   2-way LDS), V stride 132 (f4, conflict-free), S stride 65.
// ---------------------------------------------------------------------------
static constexpr int QS_STR = 132, KS_STR = 129, VS_STR = 132, SS_STR = 65;
static constexpr int SM_Q = 0;
static constexpr int SM_K = SM_Q + 64 * QS_STR;      // 8448
static constexpr int SM_V = SM_K + 64 * KS_STR;      // 16704
static constexpr int SM_S = SM_V + 64 * VS_STR;      // 25152
static constexpr int SM_M = SM_S + 64 * SS_STR;      // 29312
static constexpr int SM_L = SM_M + 64;
static constexpr int SM_C = SM_L + 64;
static constexpr int ATT_SMEM_FLOATS = SM_C + 64;    // 29504
static constexpr int ATT_SMEM_BYTES  = ATT_SMEM_FLOATS * 4;  // 118016

__global__ __launch_bounds__(256) void attn_kernel()
{
    extern __shared__ float sm[];
    int qt  = blockIdx.x;            // query tile (64 rows)
    int hq  = blockIdx.y;
    int b   = blockIdx.z;
    int kvh = hq >> 2;               // rep = Hq/Hkv = 4
    int tid = threadIdx.x;

    const float* Qg = g_qt + ((size_t)(b * HQ + hq) * S + (size_t)qt * 64) * D;
    const float* Kg = g_kt + ((size_t)(b * HKV + kvh) * S) * D;
    const float* Vg = g_vt + ((size_t)(b * HKV + kvh) * S) * D;

    const float scale = 0.08838834764831845f;  // 1/sqrt(128)

    // load Q tile (scaled)
    for (int e = tid; e < 64 * 32; e += 256) {
        int r  = e >> 5;
        int c4 = (e & 31) << 2;
        float4 q4 = *(const float4*)(Qg + (size_t)r * D + c4);
        *(float4*)&sm[SM_Q + r * QS_STR + c4] =
            make_float4(q4.x * scale, q4.y * scale, q4.z * scale, q4.w * scale);
    }
    if (tid < 64) { sm[SM_M + tid] = -INFINITY; sm[SM_L + tid] = 0.f; }

    int ty = tid >> 4;   // 0..15
    int tx = tid & 15;   // 0..15
    float o[4][8] = {};

    for (int kt = 0; kt <= qt; kt++) {
        __syncthreads();   // prior-iter consumers done; Q/init visible on iter 0

        const float* Kt = Kg + (size_t)kt * 64 * D;
        const float* Vt = Vg + (size_t)kt * 64 * D;
        for (int e = tid; e < 64 * 32; e += 256) {
            int r  = e >> 5;
            int c4 = (e & 31) << 2;
            float4 k4 = *(const float4*)(Kt + (size_t)r * D + c4);
            float* kd = &sm[SM_K + r * KS_STR + c4];
            kd[0] = k4.x; kd[1] = k4.y; kd[2] = k4.z; kd[3] = k4.w;
            float4 v4 = *(const float4*)(Vt + (size_t)r * D + c4);
            *(float4*)&sm[SM_V + r * VS_STR + c4] = v4;
        }
        __syncthreads();

        // S = Q K^T  (64x64, k over 128); 4x4 microtile per thread
        int sr = ty * 4, sc = tx * 4;
        float sacc[4][4] = {};
        #pragma unroll 4
        for (int k = 0; k < 128; k++) {
            float qa[4], kb[4];
            #pragma unroll
            for (int i = 0; i < 4; i++) qa[i] = sm[SM_Q + (sr + i) * QS_STR + k];
            #pragma unroll
            for (int j = 0; j < 4; j++) kb[j] = sm[SM_K + (sc + j) * KS_STR + k];
            #pragma unroll
            for (int i = 0; i < 4; i++)
                #pragma unroll
                for (int j = 0; j < 4; j++)
                    sacc[i][j] = fmaf(qa[i], kb[j], sacc[i][j]);
        }
        bool diag = (kt == qt);
        #pragma unroll
        for (int i = 0; i < 4; i++)
            #pragma unroll
            for (int j = 0; j < 4; j++) {
                float v = sacc[i][j];
                if (diag && (sc + j) > (sr + i)) v = -INFINITY;
                sm[SM_S + (sr + i) * SS_STR + (sc + j)] = v;
            }
        __syncthreads();

        // online softmax: one thread per row
        if (tid < 64) {
            float mold = sm[SM_M + tid];
            float mnew = mold;
            float* srow = &sm[SM_S + tid * SS_STR];
            #pragma unroll 8
            for (int c = 0; c < 64; c++) mnew = fmaxf(mnew, srow[c]);
            float corr = expf(mold - mnew);
            float l = sm[SM_L + tid] * corr;
            #pragma unroll 8
            for (int c = 0; c < 64; c++) { float p = expf(srow[c] - mnew); srow[c] = p; l += p; }
            sm[SM_M + tid] = mnew;
            sm[SM_L + tid] = l;
            sm[SM_C + tid] = corr;
        }
        __syncthreads();

        // O = O*corr + P @ V ; thread handles 4 rows x 8 cols
        int orow = ty * 4, ocol = tx * 8;
        float cr[4];
        #pragma unroll
        for (int i = 0; i < 4; i++) cr[i] = sm[SM_C + orow + i];
        #pragma unroll
        for (int i = 0; i < 4; i++)
            #pragma unroll
            for (int j = 0; j < 8; j++) o[i][j] *= cr[i];

        #pragma unroll 2
        for (int p = 0; p < 64; p++) {
            float4 v0 = *(const float4*)&sm[SM_V + p * VS_STR + ocol];
            float4 v1 = *(const float4*)&sm[SM_V + p * VS_STR + ocol + 4];
            float vv[8] = {v0.x, v0.y, v0.z, v0.w, v1.x, v1.y, v1.z, v1.w};
            float pr[4];
            #pragma unroll
            for (int i = 0; i < 4; i++) pr[i] = sm[SM_S + (orow + i) * SS_STR + p];
            #pragma unroll
            for (int i = 0; i < 4; i++)
                #pragma unroll
                for (int j = 0; j < 8; j++)
                    o[i][j] = fmaf(pr[i], vv[j], o[i][j]);
        }
    }

    // epilogue: divide by l, write to [B, S, HqD]
    float* outp = g_ao + (size_t)(b * S + qt * 64) * NQ + hq * D;
    #pragma unroll
    for (int i = 0; i < 4; i++) {
        int r = ty * 4 + i;
        float inv = 1.0f / sm[SM_L + r];
        float* op = outp + (size_t)r * NQ + tx * 8;
        *(float4*)op =
            make_float4(o[i][0] * inv, o[i][1] * inv, o[i][2] * inv, o[i][3] * inv);
        *(float4*)(op + 4) =
            make_float4(o[i][4] * inv, o[i][5] * inv, o[i][6] * inv, o[i][7] * inv);
    }
}

// ---------------------------------------------------------------------------
// Launch
// ---------------------------------------------------------------------------
extern "C" void kernel_launch(void* const* d_in, const int* in_sizes, int n_in,
                              void* d_out, int out_size)
{
    const float* x   = (const float*)d_in[0];
    const float* qw  = (const float*)d_in[1];
    const float* kw  = (const float*)d_in[2];
    const float* vw  = (const float*)d_in[3];
    const float* qb  = (const float*)d_in[4];
    const float* kb  = (const float*)d_in[5];
    const float* vb  = (const float*)d_in[6];
    const float* ow  = (const float*)d_in[7];
    const float* lnw = (const float*)d_in[8];
    float* out = (float*)d_out;

    float *h, *q, *k, *v, *qt, *kt, *vt, *ao;
    cudaGetSymbolAddress((void**)&h,  g_h);
    cudaGetSymbolAddress((void**)&q,  g_q);
    cudaGetSymbolAddress((void**)&k,  g_k);
    cudaGetSymbolAddress((void**)&v,  g_v);
    cudaGetSymbolAddress((void**)&qt, g_qt);
    cudaGetSymbolAddress((void**)&kt, g_kt);
    cudaGetSymbolAddress((void**)&vt, g_vt);
    cudaGetSymbolAddress((void**)&ao, g_ao);

    // 1) RMSNorm
    rmsnorm_kernel<<<M, 256>>>(x, lnw);

    // 2) Q/K/V projections (NT GEMM + bias)
    gemm_nt_kernel<<<dim3(NQ  / 128, M / 128), 256>>>(h, qw, qb, q, M, NQ,  H);
    gemm_nt_kernel<<<dim3(NKV / 128, M / 128), 256>>>(h, kw, kb, k, M, NKV, H);
    gemm_nt_kernel<<<dim3(NKV / 128, M / 128), 256>>>(h, vw, vb, v, M, NKV, H);

    // 3) RoPE + transpose to head-major
    rope_transpose_kernel<<<(M * HQ  * 64) / 256, 256>>>(q, qt, HQ,  1);
    rope_transpose_kernel<<<(M * HKV * 64) / 256, 256>>>(k, kt, HKV, 1);
    rope_transpose_kernel<<<(M * HKV * 64) / 256, 256>>>(v, vt, HKV, 0);

    // 4) Causal grouped attention
    cudaFuncSetAttribute(attn_kernel, cudaFuncAttributeMaxDynamicSharedMemorySize,
                         ATT_SMEM_BYTES);
    attn_kernel<<<dim3(S / 64, HQ, B), 256, ATT_SMEM_BYTES>>>();

    // 5) Output projection straight into d_out
    gemm_nt_kernel<<<dim3(H / 128, M / 128), 256>>>(ao, ow, nullptr, out, M, H, NQ);
}

// round 3
// speedup vs baseline: 1.0014x; 1.0014x over previous
#include <cuda_runtime.h>
#include <math.h>

// Problem constants
static constexpr int B   = 2;
static constexpr int S   = 2048;
static constexpr int H   = 2048;
static constexpr int HQ  = 16;
static constexpr int HKV = 4;
static constexpr int D   = 128;
static constexpr int M   = B * S;          // 4096 token rows
static constexpr int NQ  = HQ * D;         // 2048
static constexpr int NKV = HKV * D;        // 512

// ---------------------------------------------------------------------------
// Scratch (allowed: __device__ globals, no runtime allocation)
// ---------------------------------------------------------------------------
__device__ float g_h [M * H];        // rmsnorm(x)
__device__ float g_q [M * NQ];       // q = h @ Wq^T + bq   [tok, HqD]
__device__ float g_k [M * NKV];
__device__ float g_v [M * NKV];
__device__ float g_qt[M * NQ];       // [B, Hq, S, D] roped
__device__ float g_kt[M * NKV];      // [B, Hkv, S, D] roped
__device__ float g_vt[M * NKV];      // [B, Hkv, S, D]
__device__ float g_ao[M * NQ];       // attention out [B, S, HqD]

// ---------------------------------------------------------------------------
// RMSNorm: one block per token row
// ---------------------------------------------------------------------------
__global__ __launch_bounds__(256) void rmsnorm_kernel(const float* __restrict__ x,
                                                      const float* __restrict__ w)
{
    int row = blockIdx.x;
    const float* xr = x + (size_t)row * H;
    float s = 0.f;
    for (int i = threadIdx.x; i < H; i += 256) { float v = xr[i]; s += v * v; }
    __shared__ float red[8];
    #pragma unroll
    for (int o = 16; o > 0; o >>= 1) s += __shfl_down_sync(0xffffffffu, s, o);
    if ((threadIdx.x & 31) == 0) red[threadIdx.x >> 5] = s;
    __syncthreads();
    if (threadIdx.x < 8) {
        float t = red[threadIdx.x];
        #pragma unroll
        for (int o = 4; o > 0; o >>= 1) t += __shfl_down_sync(0xffu, t, o);
        if (threadIdx.x == 0) red[0] = t;
    }
    __syncthreads();
    float inv = rsqrtf(red[0] / (float)H + 1e-6f);
    float* hr = g_h + (size_t)row * H;
    for (int i = threadIdx.x; i < H; i += 256) hr[i] = xr[i] * inv * w[i];
}

// ---------------------------------------------------------------------------
// NT GEMM: C[m,n] = sum_k A[m,k] * Bm[n,k] (+ bias[n])
// A: [Mdim,Kdim] row-major, Bm: [Ndim,Kdim] row-major. All dims % 128/16 == 0.
// BM=BN=128, BK=16, 256 threads, 8x8 microtile.
// ---------------------------------------------------------------------------
__global__ __launch_bounds__(256) void gemm_nt_kernel(
    const float* __restrict__ A, const float* __restrict__ Bm,
    const float* __restrict__ bias, float* __restrict__ C,
    int Mdim, int Ndim, int Kdim)
{
    __shared__ float As[16][128];
    __shared__ float Bs[16][128];

    int tid = threadIdx.x;
    int bm = blockIdx.y * 128;
    int bn = blockIdx.x * 128;
    int tr = (tid >> 4) * 8;          // 0..120
    int tc = (tid & 15) * 8;          // 0..120
    int lr = tid >> 2;                // 0..63
    int lc = (tid & 3) << 2;          // 0,4,8,12

    const float* Ap = A  + (size_t)(bm + lr) * Kdim + lc;
    const float* Bp = Bm + (size_t)(bn + lr) * Kdim + lc;

    float acc[8][8] = {};

    for (int k0 = 0; k0 < Kdim; k0 += 16) {
        float4 a0 = *(const float4*)(Ap + k0);
        float4 a1 = *(const float4*)(Ap + (size_t)64 * Kdim + k0);
        float4 b0 = *(const float4*)(Bp + k0);
        float4 b1 = *(const float4*)(Bp + (size_t)64 * Kdim + k0);

        As[lc + 0][lr]      = a0.x; As[lc + 1][lr]      = a0.y;
        As[lc + 2][lr]      = a0.z; As[lc + 3][lr]      = a0.w;
        As[lc + 0][lr + 64] = a1.x; As[lc + 1][lr + 64] = a1.y;
        As[lc + 2][lr + 64] = a1.z; As[lc + 3][lr + 64] = a1.w;
        Bs[lc + 0][lr]      = b0.x; Bs[lc + 1][lr]      = b0.y;
        Bs[lc + 2][lr]      = b0.z; Bs[lc + 3][lr]      = b0.w;
        Bs[lc + 0][lr + 64] = b1.x; Bs[lc + 1][lr + 64] = b1.y;
        Bs[lc + 2][lr + 64] = b1.z; Bs[lc + 3][lr + 64] = b1.w;
        __syncthreads();

        #pragma unroll
        for (int k = 0; k < 16; k++) {
            float4 va0 = *(const float4*)&As[k][tr];
            float4 va1 = *(const float4*)&As[k][tr + 4];
            float4 vb0 = *(const float4*)&Bs[k][tc];
            float4 vb1 = *(const float4*)&Bs[k][tc + 4];
            float ar[8] = {va0.x, va0.y, va0.z, va0.w, va1.x, va1.y, va1.z, va1.w};
            float br[8] = {vb0.x, vb0.y, vb0.z, vb0.w, vb1.x, vb1.y, vb1.z, vb1.w};
            #pragma unroll
            for (int i = 0; i < 8; i++)
                #pragma unroll
                for (int j = 0; j < 8; j++)
                    acc[i][j] = fmaf(ar[i], br[j], acc[i][j]);
        }
        __syncthreads();
    }

    float bv[8];
    #pragma unroll
    for (int j = 0; j < 8; j++) bv[j] = bias ? bias[bn + tc + j] : 0.f;

    #pragma unroll
    for (int i = 0; i < 8; i++) {
        float* cp = C + (size_t)(bm + tr + i) * Ndim + bn + tc;
        float4 w0 = make_float4(acc[i][0] + bv[0], acc[i][1] + bv[1],
                                acc[i][2] + bv[2], acc[i][3] + bv[3]);
        float4 w1 = make_float4(acc[i][4] + bv[4], acc[i][5] + bv[5],
                                acc[i][6] + bv[6], acc[i][7] + bv[7]);
        *(float4*)cp = w0;
        *(float4*)(cp + 4) = w1;
    }
}

// ---------------------------------------------------------------------------
// RoPE (rotate-half) + transpose [B,S,Hh,D] -> [B,Hh,S,D]
// one thread per (b, s, h, i<64): handles pair (i, i+64)
// ---------------------------------------------------------------------------
__global__ __launch_bounds__(256) void rope_transpose_kernel(
    const float* __restrict__ in, float* __restrict__ out, int Hh, int do_rope)
{
    int id = blockIdx.x * 256 + threadIdx.x;
    int i  = id & 63;
    int h  = (id >> 6) % Hh;
    int rest = id / (64 * Hh);
    int s  = rest % S;
    int b  = rest / S;

    const float* ip = in + ((size_t)(b * S + s) * Hh + h) * D;
    float t1 = ip[i];
    float t2 = ip[i + 64];
    float* op = out + ((size_t)(b * Hh + h) * S + s) * D;

    if (do_rope) {
        // inv_freq = 10000^{-i/64}
        float inv = exp2f(-(float)i * (13.287712379549449f / 64.0f));
        float ang = (float)s * inv;
        float sn, cs;
        sincosf(ang, &sn, &cs);
        op[i]      = t1 * cs - t2 * sn;
        op[i + 64] = t2 * cs + t1 * sn;
    } else {
        op[i]      = t1;
        op[i + 64] = t2;
    }
}

// ---------------------------------------------------------------------------
// Causal flash attention (fp32). One block = 64 query rows of one (b, hq).
// Smem strides chosen for conflict behavior:
//   Q stride 132 (f4 ld/st, broadcast reads), K stride 129 (scalar STS,
//   2-way LDS), V stride 132 (f4, conflict-free), S stride 65.
// ---------------------------------------------------------------------------
static constexpr int QS_STR = 132, KS_STR = 129, VS_STR = 132, SS_STR = 65;
static constexpr int SM_Q = 0;
static constexpr int SM_K = SM_Q + 64 * QS_STR;      // 8448
static constexpr int SM_V = SM_K + 64 * KS_STR;      // 16704
static constexpr int SM_S = SM_V + 64 * VS_STR;      // 25152
static constexpr int SM_M = SM_S + 64 * SS_STR;      // 29312
static constexpr int SM_L = SM_M + 64;
static constexpr int SM_C = SM_L + 64;
static constexpr int ATT_SMEM_FLOATS = SM_C + 64;    // 29504
static constexpr int ATT_SMEM_BYTES  = ATT_SMEM_FLOATS * 4;  // 118016

__global__ __launch_bounds__(256) void attn_kernel()
{
    extern __shared__ float sm[];
    int qt  = blockIdx.x;            // query tile (64 rows)
    int hq  = blockIdx.y;
    int b   = blockIdx.z;
    int kvh = hq >> 2;               // rep = Hq/Hkv = 4
    int tid = threadIdx.x;

    const float* Qg = g_qt + ((size_t)(b * HQ + hq) * S + (size_t)qt * 64) * D;
    const float* Kg = g_kt + ((size_t)(b * HKV + kvh) * S) * D;
    const float* Vg = g_vt + ((size_t)(b * HKV + kvh) * S) * D;

    const float scale = 0.08838834764831845f;  // 1/sqrt(128)

    // load Q tile (scaled)
    for (int e = tid; e < 64 * 32; e += 256) {
        int r  = e >> 5;
        int c4 = (e & 31) << 2;
        float4 q4 = *(const float4*)(Qg + (size_t)r * D + c4);
        *(float4*)&sm[SM_Q + r * QS_STR + c4] =
            make_float4(q4.x * scale, q4.y * scale, q4.z * scale, q4.w * scale);
    }
    if (tid < 64) { sm[SM_M + tid] = -INFINITY; sm[SM_L + tid] = 0.f; }

    int ty = tid >> 4;   // 0..15
    int tx = tid & 15;   // 0..15
    float o[4][8] = {};

    for (int kt = 0; kt <= qt; kt++) {
        __syncthreads();   // prior-iter consumers done; Q/init visible on iter 0

        const float* Kt = Kg + (size_t)kt * 64 * D;
        const float* Vt = Vg + (size_t)kt * 64 * D;
        for (int e = tid; e < 64 * 32; e += 256) {
            int r  = e >> 5;
            int c4 = (e & 31) << 2;
            float4 k4 = *(const float4*)(Kt + (size_t)r * D + c4);
            float* kd = &sm[SM_K + r * KS_STR + c4];
            kd[0] = k4.x; kd[1] = k4.y; kd[2] = k4.z; kd[3] = k4.w;
            float4 v4 = *(const float4*)(Vt + (size_t)r * D + c4);
            *(float4*)&sm[SM_V + r * VS_STR + c4] = v4;
        }
        __syncthreads();

        // S = Q K^T  (64x64, k over 128); 4x4 microtile per thread
        int sr = ty * 4, sc = tx * 4;
        float sacc[4][4] = {};
        #pragma unroll 4
        for (int k = 0; k < 128; k++) {
            float qa[4], kb[4];
            #pragma unroll
            for (int i = 0; i < 4; i++) qa[i] = sm[SM_Q + (sr + i) * QS_STR + k];
            #pragma unroll
            for (int j = 0; j < 4; j++) kb[j] = sm[SM_K + (sc + j) * KS_STR + k];
            #pragma unroll
            for (int i = 0; i < 4; i++)
                #pragma unroll
                for (int j = 0; j < 4; j++)
                    sacc[i][j] = fmaf(qa[i], kb[j], sacc[i][j]);
        }
        bool diag = (kt == qt);
        #pragma unroll
        for (int i = 0; i < 4; i++)
            #pragma unroll
            for (int j = 0; j < 4; j++) {
                float v = sacc[i][j];
                if (diag && (sc + j) > (sr + i)) v = -INFINITY;
                sm[SM_S + (sr + i) * SS_STR + (sc + j)] = v;
            }
        __syncthreads();

        // online softmax: one thread per row
        if (tid < 64) {
            float mold = sm[SM_M + tid];
            float mnew = mold;
            float* srow = &sm[SM_S + tid * SS_STR];
            #pragma unroll 8
            for (int c = 0; c < 64; c++) mnew = fmaxf(mnew, srow[c]);
            float corr = expf(mold - mnew);
            float l = sm[SM_L + tid] * corr;
            #pragma unroll 8
            for (int c = 0; c < 64; c++) { float p = expf(srow[c] - mnew); srow[c] = p; l += p; }
            sm[SM_M + tid] = mnew;
            sm[SM_L + tid] = l;
            sm[SM_C + tid] = corr;
        }
        __syncthreads();

        // O = O*corr + P @ V ; thread handles 4 rows x 8 cols
        int orow = ty * 4, ocol = tx * 8;
        float cr[4];
        #pragma unroll
        for (int i = 0; i < 4; i++) cr[i] = sm[SM_C + orow + i];
        #pragma unroll
        for (int i = 0; i < 4; i++)
            #pragma unroll
            for (int j = 0; j < 8; j++) o[i][j] *= cr[i];

        #pragma unroll 2
        for (int p = 0; p < 64; p++) {
            float4 v0 = *(const float4*)&sm[SM_V + p * VS_STR + ocol];
            float4 v1 = *(const float4*)&sm[SM_V + p * VS_STR + ocol + 4];
            float vv[8] = {v0.x, v0.y, v0.z, v0.w, v1.x, v1.y, v1.z, v1.w};
            float pr[4];
            #pragma unroll
            for (int i = 0; i < 4; i++) pr[i] = sm[SM_S + (orow + i) * SS_STR + p];
            #pragma unroll
            for (int i = 0; i < 4; i++)
                #pragma unroll
                for (int j = 0; j < 8; j++)
                    o[i][j] = fmaf(pr[i], vv[j], o[i][j]);
        }
    }

    // epilogue: divide by l, write to [B, S, HqD]
    float* outp = g_ao + (size_t)(b * S + qt * 64) * NQ + hq * D;
    #pragma unroll
    for (int i = 0; i < 4; i++) {
        int r = ty * 4 + i;
        float inv = 1.0f / sm[SM_L + r];
        float* op = outp + (size_t)r * NQ + tx * 8;
        *(float4*)op =
            make_float4(o[i][0] * inv, o[i][1] * inv, o[i][2] * inv, o[i][3] * inv);
        *(float4*)(op + 4) =
            make_float4(o[i][4] * inv, o[i][5] * inv, o[i][6] * inv, o[i][7] * inv);
    }
}

// ---------------------------------------------------------------------------
// Launch
// ---------------------------------------------------------------------------
extern "C" void kernel_launch(void* const* d_in, const int* in_sizes, int n_in,
                              void* d_out, int out_size)
{
    const float* x   = (const float*)d_in[0];
    const float* qw  = (const float*)d_in[1];
    const float* kw  = (const float*)d_in[2];
    const float* vw  = (const float*)d_in[3];
    const float* qb  = (const float*)d_in[4];
    const float* kb  = (const float*)d_in[5];
    const float* vb  = (const float*)d_in[6];
    const float* ow  = (const float*)d_in[7];
    const float* lnw = (const float*)d_in[8];
    float* out = (float*)d_out;

    float *h, *q, *k, *v, *qt, *kt, *vt, *ao;
    cudaGetSymbolAddress((void**)&h,  g_h);
    cudaGetSymbolAddress((void**)&q,  g_q);
    cudaGetSymbolAddress((void**)&k,  g_k);
    cudaGetSymbolAddress((void**)&v,  g_v);
    cudaGetSymbolAddress((void**)&qt, g_qt);
    cudaGetSymbolAddress((void**)&kt, g_kt);
    cudaGetSymbolAddress((void**)&vt, g_vt);
    cudaGetSymbolAddress((void**)&ao, g_ao);

    // 1) RMSNorm
    rmsnorm_kernel<<<M, 256>>>(x, lnw);

    // 2) Q/K/V projections (NT GEMM + bias)
    gemm_nt_kernel<<<dim3(NQ  / 128, M / 128), 256>>>(h, qw, qb, q, M, NQ,  H);
    gemm_nt_kernel<<<dim3(NKV / 128, M / 128), 256>>>(h, kw, kb, k, M, NKV, H);
    gemm_nt_kernel<<<dim3(NKV / 128, M / 128), 256>>>(h, vw, vb, v, M, NKV, H);

    // 3) RoPE + transpose to head-major
    rope_transpose_kernel<<<(M * HQ  * 64) / 256, 256>>>(q, qt, HQ,  1);
    rope_transpose_kernel<<<(M * HKV * 64) / 256, 256>>>(k, kt, HKV, 1);
    rope_transpose_kernel<<<(M * HKV * 64) / 256, 256>>>(v, vt, HKV, 0);

    // 4) Causal grouped attention
    cudaFuncSetAttribute(attn_kernel, cudaFuncAttributeMaxDynamicSharedMemorySize,
                         ATT_SMEM_BYTES);
    attn_kernel<<<dim3(S / 64, HQ, B), 256, ATT_SMEM_BYTES>>>();

    // 5) Output projection straight into d_out
    gemm_nt_kernel<<<dim3(H / 128, M / 128), 256>>>(ao, ow, nullptr, out, M, H, NQ);
}

// round 5
// speedup vs baseline: 1.5069x; 1.5048x over previous
#include <cuda_runtime.h>
#include <cuda_bf16.h>
#include <math.h>
#include <stdint.h>

// Problem constants
static constexpr int B   = 2;
static constexpr int S   = 2048;
static constexpr int H   = 2048;
static constexpr int HQ  = 16;
static constexpr int HKV = 4;
static constexpr int D   = 128;
static constexpr int M   = B * S;          // 4096 token rows
static constexpr int NQ  = HQ * D;         // 2048
static constexpr int NKV = HKV * D;        // 512

// ---------------------------------------------------------------------------
// Scratch (allowed: __device__ globals, no runtime allocation)
// ---------------------------------------------------------------------------
__device__ __nv_bfloat16 g_h_hi [M * H];
__device__ __nv_bfloat16 g_h_lo [M * H];
__device__ __nv_bfloat16 g_qw_hi[NQ * H];
__device__ __nv_bfloat16 g_qw_lo[NQ * H];
__device__ __nv_bfloat16 g_kw_hi[NKV * H];
__device__ __nv_bfloat16 g_kw_lo[NKV * H];
__device__ __nv_bfloat16 g_vw_hi[NKV * H];
__device__ __nv_bfloat16 g_vw_lo[NKV * H];
__device__ __nv_bfloat16 g_ow_hi[H * NQ];
__device__ __nv_bfloat16 g_ow_lo[H * NQ];
__device__ __nv_bfloat16 g_ao_hi[M * NQ];
__device__ __nv_bfloat16 g_ao_lo[M * NQ];

__device__ float g_q [M * NQ];
__device__ float g_k [M * NKV];
__device__ float g_v [M * NKV];
__device__ float g_qt[M * NQ];       // [B, Hq, S, D] roped
__device__ float g_kt[M * NKV];      // [B, Hkv, S, D] roped
__device__ float g_vt[M * NKV];      // [B, Hkv, S, D]

// ---------------------------------------------------------------------------
// cp.async helpers (baseline PTX, valid on compute_100)
// ---------------------------------------------------------------------------
__device__ __forceinline__ uint32_t smem_u32(const void* p) {
    uint32_t a;
    asm("{ .reg .u64 t; cvta.to.shared.u64 t, %1; cvt.u32.u64 %0, t; }"
        : "=r"(a) : "l"(p));
    return a;
}
__device__ __forceinline__ void cp_async16(uint32_t dst, const void* src) {
    asm volatile("cp.async.cg.shared.global [%0], [%1], 16;"
                 :: "r"(dst), "l"(src));
}
__device__ __forceinline__ void cp_async_commit() {
    asm volatile("cp.async.commit_group;" ::: "memory");
}
template <int N>
__device__ __forceinline__ void cp_async_wait() {
    asm volatile("cp.async.wait_group %0;" :: "n"(N) : "memory");
}

// mma.sync m16n8k16 bf16 -> f32 (baseline PTX tensor core path)
__device__ __forceinline__ void mma16816(float* d, const uint32_t* a, const uint32_t* b) {
    asm volatile(
        "mma.sync.aligned.m16n8k16.row.col.f32.bf16.bf16.f32 "
        "{%0,%1,%2,%3}, {%4,%5,%6,%7}, {%8,%9}, {%0,%1,%2,%3};"
        : "+f"(d[0]), "+f"(d[1]), "+f"(d[2]), "+f"(d[3])
        : "r"(a[0]), "r"(a[1]), "r"(a[2]), "r"(a[3]), "r"(b[0]), "r"(b[1]));
}

// ---------------------------------------------------------------------------
// fp32 -> (bf16 hi, bf16 lo) split
// ---------------------------------------------------------------------------
__global__ __launch_bounds__(256) void split_kernel(const float* __restrict__ in,
                                                    __nv_bfloat16* __restrict__ hi,
                                                    __nv_bfloat16* __restrict__ lo,
                                                    int n)
{
    int i = blockIdx.x * 256 + threadIdx.x;
    if (i < n) {
        float v = in[i];
        __nv_bfloat16 h = __float2bfloat16(v);
        hi[i] = h;
        lo[i] = __float2bfloat16(v - __bfloat162float(h));
    }
}

// ---------------------------------------------------------------------------
// RMSNorm: one block per token row -> bf16 hi/lo output
// ---------------------------------------------------------------------------
__global__ __launch_bounds__(256) void rmsnorm_kernel(const float* __restrict__ x,
                                                      const float* __restrict__ w)
{
    int row = blockIdx.x;
    const float* xr = x + (size_t)row * H;
    float s = 0.f;
    for (int i = threadIdx.x; i < H; i += 256) { float v = xr[i]; s += v * v; }
    __shared__ float red[8];
    #pragma unroll
    for (int o = 16; o > 0; o >>= 1) s += __shfl_down_sync(0xffffffffu, s, o);
    if ((threadIdx.x & 31) == 0) red[threadIdx.x >> 5] = s;
    __syncthreads();
    if (threadIdx.x < 8) {
        float t = red[threadIdx.x];
        #pragma unroll
        for (int o = 4; o > 0; o >>= 1) t += __shfl_down_sync(0xffu, t, o);
        if (threadIdx.x == 0) red[0] = t;
    }
    __syncthreads();
    float inv = rsqrtf(red[0] / (float)H + 1e-6f);
    __nv_bfloat16* hh = g_h_hi + (size_t)row * H;
    __nv_bfloat16* hl = g_h_lo + (size_t)row * H;
    for (int i = threadIdx.x; i < H; i += 256) {
        float v = xr[i] * inv * w[i];
        __nv_bfloat16 hv = __float2bfloat16(v);
        hh[i] = hv;
        hl[i] = __float2bfloat16(v - __bfloat162float(hv));
    }
}

// ---------------------------------------------------------------------------
// Tensor-core GEMM (NT): C[m,n] = sum_k A[m,k]*B[n,k] (+bias[n]) in fp32
// via bf16x3 split: Ahi*Bhi + Ahi*Blo + Alo*Bhi.
// 128x128x32 CTA tile, 8 warps (2x4), warp tile 64x32 = 4x4 m16n8k16.
// Double-buffered cp.async stages; smem row stride 40 bf16 (conflict-free).
// ---------------------------------------------------------------------------
static constexpr int GM_BK     = 32;
static constexpr int GM_LDS    = 40;                       // bf16 stride per row
static constexpr int TILE_E    = 128 * GM_LDS;             // 5120 bf16 per tile
static constexpr int STAGE_E   = 4 * TILE_E;               // Ahi,Alo,Bhi,Blo
static constexpr int GM_SMEM_BYTES = 2 * STAGE_E * 2;      // 81920

__device__ __forceinline__ void gm_load_stage(
    __nv_bfloat16* st, const __nv_bfloat16* Ahi, const __nv_bfloat16* Alo,
    const __nv_bfloat16* Bhi, const __nv_bfloat16* Blo,
    int bm, int bn, int k0, int ldK, int tid)
{
    // per tile: 128 rows x 32 k = 512 x 16B vectors; 256 threads x 2 vectors
    const __nv_bfloat16* srcs[4] = {
        Ahi + (size_t)bm * ldK + k0, Alo + (size_t)bm * ldK + k0,
        Bhi + (size_t)bn * ldK + k0, Blo + (size_t)bn * ldK + k0 };
    #pragma unroll
    for (int t = 0; t < 4; t++) {
        uint32_t dbase = smem_u32(st + t * TILE_E);
        #pragma unroll
        for (int i = 0; i < 2; i++) {
            int v  = tid + i * 256;
            int r  = v >> 2;
            int cv = v & 3;
            cp_async16(dbase + (uint32_t)(r * GM_LDS + cv * 8) * 2,
                       srcs[t] + (size_t)r * ldK + cv * 8);
        }
    }
    cp_async_commit();
}

__global__ __launch_bounds__(256) void gemm_mma_kernel(
    const __nv_bfloat16* __restrict__ Ahi, const __nv_bfloat16* __restrict__ Alo,
    const __nv_bfloat16* __restrict__ Bhi, const __nv_bfloat16* __restrict__ Blo,
    const float* __restrict__ bias, float* __restrict__ C,
    int Ndim, int Kdim)
{
    extern __shared__ __nv_bfloat16 sm[];
    int tid = threadIdx.x;
    int wid = tid >> 5, lane = tid & 31;
    int grp = lane >> 2, qd = lane & 3;
    int bm = blockIdx.y * 128, bn = blockIdx.x * 128;
    int wm = (wid & 1) * 64;     // warp row offset within CTA tile
    int wn = (wid >> 1) * 32;    // warp col offset

    const int NC = Kdim / GM_BK;

    float acc[4][4][4] = {};

    gm_load_stage(sm, Ahi, Alo, Bhi, Blo, bm, bn, 0, Kdim, tid);

    for (int c = 0; c < NC; c++) {
        __nv_bfloat16* st = sm + (c & 1) * STAGE_E;
        if (c + 1 < NC) {
            gm_load_stage(sm + ((c + 1) & 1) * STAGE_E, Ahi, Alo, Bhi, Blo,
                          bm, bn, (c + 1) * GM_BK, Kdim, tid);
            cp_async_wait<1>();
        } else {
            cp_async_wait<0>();
        }
        __syncthreads();

        const __nv_bfloat16* tAhi = st;
        const __nv_bfloat16* tAlo = st + TILE_E;
        const __nv_bfloat16* tBhi = st + 2 * TILE_E;
        const __nv_bfloat16* tBlo = st + 3 * TILE_E;

        #pragma unroll
        for (int ks = 0; ks < 2; ks++) {
            int kb = ks * 16 + qd * 2;
            uint32_t ahi[4][4], alo[4][4], bhi[4][2], blo[4][2];
            #pragma unroll
            for (int mt = 0; mt < 4; mt++) {
                int r0 = wm + mt * 16 + grp;
                ahi[mt][0] = *(const uint32_t*)(tAhi + r0 * GM_LDS + kb);
                ahi[mt][1] = *(const uint32_t*)(tAhi + (r0 + 8) * GM_LDS + kb);
                ahi[mt][2] = *(const uint32_t*)(tAhi + r0 * GM_LDS + kb + 8);
                ahi[mt][3] = *(const uint32_t*)(tAhi + (r0 + 8) * GM_LDS + kb + 8);
                alo[mt][0] = *(const uint32_t*)(tAlo + r0 * GM_LDS + kb);
                alo[mt][1] = *(const uint32_t*)(tAlo + (r0 + 8) * GM_LDS + kb);
                alo[mt][2] = *(const uint32_t*)(tAlo + r0 * GM_LDS + kb + 8);
                alo[mt][3] = *(const uint32_t*)(tAlo + (r0 + 8) * GM_LDS + kb + 8);
            }
            #pragma unroll
            for (int nt = 0; nt < 4; nt++) {
                int n0 = wn + nt * 8 + grp;
                bhi[nt][0] = *(const uint32_t*)(tBhi + n0 * GM_LDS + kb);
                bhi[nt][1] = *(const uint32_t*)(tBhi + n0 * GM_LDS + kb + 8);
                blo[nt][0] = *(const uint32_t*)(tBlo + n0 * GM_LDS + kb);
                blo[nt][1] = *(const uint32_t*)(tBlo + n0 * GM_LDS + kb + 8);
            }
            #pragma unroll
            for (int mt = 0; mt < 4; mt++)
                #pragma unroll
                for (int nt = 0; nt < 4; nt++) {
                    mma16816(acc[mt][nt], ahi[mt], bhi[nt]);
                    mma16816(acc[mt][nt], ahi[mt], blo[nt]);
                    mma16816(acc[mt][nt], alo[mt], bhi[nt]);
                }
        }
        __syncthreads();
    }

    // epilogue: d frag -> C (+bias)
    #pragma unroll
    for (int mt = 0; mt < 4; mt++) {
        int row0 = bm + wm + mt * 16 + grp;
        #pragma unroll
        for (int nt = 0; nt < 4; nt++) {
            int col0 = bn + wn + nt * 8 + qd * 2;
            float b0 = bias ? bias[col0]     : 0.f;
            float b1 = bias ? bias[col0 + 1] : 0.f;
            float* c0 = C + (size_t)row0 * Ndim + col0;
            float* c1 = C + (size_t)(row0 + 8) * Ndim + col0;
            *(float2*)c0 = make_float2(acc[mt][nt][0] + b0, acc[mt][nt][1] + b1);
            *(float2*)c1 = make_float2(acc[mt][nt][2] + b0, acc[mt][nt][3] + b1);
        }
    }
}

// ---------------------------------------------------------------------------
// RoPE (rotate-half) + transpose [B,S,Hh,D] -> [B,Hh,S,D]
// ---------------------------------------------------------------------------
__global__ __launch_bounds__(256) void rope_transpose_kernel(
    const float* __restrict__ in, float* __restrict__ out, int Hh, int do_rope)
{
    int id = blockIdx.x * 256 + threadIdx.x;
    int i  = id & 63;
    int h  = (id >> 6) % Hh;
    int rest = id / (64 * Hh);
    int s  = rest % S;
    int b  = rest / S;

    const float* ip = in + ((size_t)(b * S + s) * Hh + h) * D;
    float t1 = ip[i];
    float t2 = ip[i + 64];
    float* op = out + ((size_t)(b * Hh + h) * S + s) * D;

    if (do_rope) {
        float inv = exp2f(-(float)i * (13.287712379549449f / 64.0f));
        float ang = (float)s * inv;
        float sn, cs;
        sincosf(ang, &sn, &cs);
        op[i]      = t1 * cs - t2 * sn;
        op[i + 64] = t2 * cs + t1 * sn;
    } else {
        op[i]      = t1;
        op[i + 64] = t2;
    }
}

// ---------------------------------------------------------------------------
// Causal flash attention (fp32 SIMT). One block = 64 query rows of one (b, hq).
// Epilogue writes bf16 hi/lo for the tensor-core O projection.
// ---------------------------------------------------------------------------
static constexpr int QS_STR = 132, KS_STR = 129, VS_STR = 132, SS_STR = 65;
static constexpr int SM_Q = 0;
static constexpr int SM_K = SM_Q + 64 * QS_STR;
static constexpr int SM_V = SM_K + 64 * KS_STR;
static constexpr int SM_S = SM_V + 64 * VS_STR;
static constexpr int SM_M = SM_S + 64 * SS_STR;
static constexpr int SM_L = SM_M + 64;
static constexpr int SM_C = SM_L + 64;
static constexpr int ATT_SMEM_FLOATS = SM_C + 64;
static constexpr int ATT_SMEM_BYTES  = ATT_SMEM_FLOATS * 4;

__global__ __launch_bounds__(256) void attn_kernel()
{
    extern __shared__ float smf[];
    float* sm = smf;
    int qt  = blockIdx.x;
    int hq  = blockIdx.y;
    int b   = blockIdx.z;
    int kvh = hq >> 2;
    int tid = threadIdx.x;

    const float* Qg = g_qt + ((size_t)(b * HQ + hq) * S + (size_t)qt * 64) * D;
    const float* Kg = g_kt + ((size_t)(b * HKV + kvh) * S) * D;
    const float* Vg = g_vt + ((size_t)(b * HKV + kvh) * S) * D;

    const float scale = 0.08838834764831845f;

    for (int e = tid; e < 64 * 32; e += 256) {
        int r  = e >> 5;
        int c4 = (e & 31) << 2;
        float4 q4 = *(const float4*)(Qg + (size_t)r * D + c4);
        *(float4*)&sm[SM_Q + r * QS_STR + c4] =
            make_float4(q4.x * scale, q4.y * scale, q4.z * scale, q4.w * scale);
    }
    if (tid < 64) { sm[SM_M + tid] = -INFINITY; sm[SM_L + tid] = 0.f; }

    int ty = tid >> 4;
    int tx = tid & 15;
    float o[4][8] = {};

    for (int kt = 0; kt <= qt; kt++) {
        __syncthreads();

        const float* Kt = Kg + (size_t)kt * 64 * D;
        const float* Vt = Vg + (size_t)kt * 64 * D;
        for (int e = tid; e < 64 * 32; e += 256) {
            int r  = e >> 5;
            int c4 = (e & 31) << 2;
            float4 k4 = *(const float4*)(Kt + (size_t)r * D + c4);
            float* kd = &sm[SM_K + r * KS_STR + c4];
            kd[0] = k4.x; kd[1] = k4.y; kd[2] = k4.z; kd[3] = k4.w;
            float4 v4 = *(const float4*)(Vt + (size_t)r * D + c4);
            *(float4*)&sm[SM_V + r * VS_STR + c4] = v4;
        }
        __syncthreads();

        int sr = ty * 4, sc = tx * 4;
        float sacc[4][4] = {};
        #pragma unroll 4
        for (int k = 0; k < 128; k++) {
            float qa[4], kb[4];
            #pragma unroll
            for (int i = 0; i < 4; i++) qa[i] = sm[SM_Q + (sr + i) * QS_STR + k];
            #pragma unroll
            for (int j = 0; j < 4; j++) kb[j] = sm[SM_K + (sc + j) * KS_STR + k];
            #pragma unroll
            for (int i = 0; i < 4; i++)
                #pragma unroll
                for (int j = 0; j < 4; j++)
                    sacc[i][j] = fmaf(qa[i], kb[j], sacc[i][j]);
        }
        bool diag = (kt == qt);
        #pragma unroll
        for (int i = 0; i < 4; i++)
            #pragma unroll
            for (int j = 0; j < 4; j++) {
                float v = sacc[i][j];
                if (diag && (sc + j) > (sr + i)) v = -INFINITY;
                sm[SM_S + (sr + i) * SS_STR + (sc + j)] = v;
            }
        __syncthreads();

        if (tid < 64) {
            float mold = sm[SM_M + tid];
            float mnew = mold;
            float* srow = &sm[SM_S + tid * SS_STR];
            #pragma unroll 8
            for (int c = 0; c < 64; c++) mnew = fmaxf(mnew, srow[c]);
            float corr = expf(mold - mnew);
            float l = sm[SM_L + tid] * corr;
            #pragma unroll 8
            for (int c = 0; c < 64; c++) { float p = expf(srow[c] - mnew); srow[c] = p; l += p; }
            sm[SM_M + tid] = mnew;
            sm[SM_L + tid] = l;
            sm[SM_C + tid] = corr;
        }
        __syncthreads();

        int orow = ty * 4, ocol = tx * 8;
        float cr[4];
        #pragma unroll
        for (int i = 0; i < 4; i++) cr[i] = sm[SM_C + orow + i];
        #pragma unroll
        for (int i = 0; i < 4; i++)
            #pragma unroll
            for (int j = 0; j < 8; j++) o[i][j] *= cr[i];

        #pragma unroll 2
        for (int p = 0; p < 64; p++) {
            float4 v0 = *(const float4*)&sm[SM_V + p * VS_STR + ocol];
            float4 v1 = *(const float4*)&sm[SM_V + p * VS_STR + ocol + 4];
            float vv[8] = {v0.x, v0.y, v0.z, v0.w, v1.x, v1.y, v1.z, v1.w};
            float pr[4];
            #pragma unroll
            for (int i = 0; i < 4; i++) pr[i] = sm[SM_S + (orow + i) * SS_STR + p];
            #pragma unroll
            for (int i = 0; i < 4; i++)
                #pragma unroll
                for (int j = 0; j < 8; j++)
                    o[i][j] = fmaf(pr[i], vv[j], o[i][j]);
        }
    }

    // epilogue: divide by l, split into bf16 hi/lo for O projection
    size_t rowbase = (size_t)(b * S + qt * 64) * NQ + hq * D;
    #pragma unroll
    for (int i = 0; i < 4; i++) {
        int r = ty * 4 + i;
        float inv = 1.0f / sm[SM_L + r];
        size_t off = rowbase + (size_t)r * NQ + tx * 8;
        #pragma unroll
        for (int j = 0; j < 8; j++) {
            float v = o[i][j] * inv;
            __nv_bfloat16 hv = __float2bfloat16(v);
            g_ao_hi[off + j] = hv;
            g_ao_lo[off + j] = __float2bfloat16(v - __bfloat162float(hv));
        }
    }
}

// ---------------------------------------------------------------------------
// Launch
// ---------------------------------------------------------------------------
extern "C" void kernel_launch(void* const* d_in, const int* in_sizes, int n_in,
                              void* d_out, int out_size)
{
    const float* x   = (const float*)d_in[0];
    const float* qw  = (const float*)d_in[1];
    const float* kw  = (const float*)d_in[2];
    const float* vw  = (const float*)d_in[3];
    const float* qb  = (const float*)d_in[4];
    const float* kb  = (const float*)d_in[5];
    const float* vb  = (const float*)d_in[6];
    const float* ow  = (const float*)d_in[7];
    const float* lnw = (const float*)d_in[8];
    float* out = (float*)d_out;

    __nv_bfloat16 *hhi, *hlo, *qwh, *qwl, *kwh, *kwl, *vwh, *vwl, *owh, *owl, *aoh, *aol;
    float *q, *k, *v, *qt, *kt, *vt;
    cudaGetSymbolAddress((void**)&hhi, g_h_hi);
    cudaGetSymbolAddress((void**)&hlo, g_h_lo);
    cudaGetSymbolAddress((void**)&qwh, g_qw_hi);
    cudaGetSymbolAddress((void**)&qwl, g_qw_lo);
    cudaGetSymbolAddress((void**)&kwh, g_kw_hi);
    cudaGetSymbolAddress((void**)&kwl, g_kw_lo);
    cudaGetSymbolAddress((void**)&vwh, g_vw_hi);
    cudaGetSymbolAddress((void**)&vwl, g_vw_lo);
    cudaGetSymbolAddress((void**)&owh, g_ow_hi);
    cudaGetSymbolAddress((void**)&owl, g_ow_lo);
    cudaGetSymbolAddress((void**)&aoh, g_ao_hi);
    cudaGetSymbolAddress((void**)&aol, g_ao_lo);
    cudaGetSymbolAddress((void**)&q,  g_q);
    cudaGetSymbolAddress((void**)&k,  g_k);
    cudaGetSymbolAddress((void**)&v,  g_v);
    cudaGetSymbolAddress((void**)&qt, g_qt);
    cudaGetSymbolAddress((void**)&kt, g_kt);
    cudaGetSymbolAddress((void**)&vt, g_vt);

    cudaFuncSetAttribute(gemm_mma_kernel, cudaFuncAttributeMaxDynamicSharedMemorySize,
                         GM_SMEM_BYTES);
    cudaFuncSetAttribute(attn_kernel, cudaFuncAttributeMaxDynamicSharedMemorySize,
                         ATT_SMEM_BYTES);

    // 0) Split weights into bf16 hi/lo
    split_kernel<<<(NQ  * H + 255) / 256, 256>>>(qw, qwh, qwl, NQ  * H);
    split_kernel<<<(NKV * H + 255) / 256, 256>>>(kw, kwh, kwl, NKV * H);
    split_kernel<<<(NKV * H + 255) / 256, 256>>>(vw, vwh, vwl, NKV * H);
    split_kernel<<<(H  * NQ + 255) / 256, 256>>>(ow, owh, owl, H  * NQ);

    // 1) RMSNorm -> bf16 hi/lo
    rmsnorm_kernel<<<M, 256>>>(x, lnw);

    // 2) Q/K/V projections on tensor cores (bf16x3 via mma.sync)
    gemm_mma_kernel<<<dim3(NQ  / 128, M / 128), 256, GM_SMEM_BYTES>>>(
        hhi, hlo, qwh, qwl, qb, q, NQ,  H);
    gemm_mma_kernel<<<dim3(NKV / 128, M / 128), 256, GM_SMEM_BYTES>>>(
        hhi, hlo, kwh, kwl, kb, k, NKV, H);
    gemm_mma_kernel<<<dim3(NKV / 128, M / 128), 256, GM_SMEM_BYTES>>>(
        hhi, hlo, vwh, vwl, vb, v, NKV, H);

    // 3) RoPE + transpose to head-major
    rope_transpose_kernel<<<(M * HQ  * 64) / 256, 256>>>(q, qt, HQ,  1);
    rope_transpose_kernel<<<(M * HKV * 64) / 256, 256>>>(k, kt, HKV, 1);
    rope_transpose_kernel<<<(M * HKV * 64) / 256, 256>>>(v, vt, HKV, 0);

    // 4) Causal grouped attention (writes bf16 hi/lo attention output)
    attn_kernel<<<dim3(S / 64, HQ, B), 256, ATT_SMEM_BYTES>>>();

    // 5) Output projection on tensor cores straight into d_out
    gemm_mma_kernel<<<dim3(H / 128, M / 128), 256, GM_SMEM_BYTES>>>(
        aoh, aol, owh, owl, nullptr, out, H, NQ);
}